// round 10
// baseline (speedup 1.0000x reference)
#include <cuda_runtime.h>
#include <cstdint>

#define HORSES 18
#define TILE 32
#define STAGES 4
#define NUM_SMS 148
#define CTAS_PER_SM 6

#define SC_BYTES (TILE * HORSES * 3 * 4)   /* 6912 */
#define RK_BYTES (TILE * HORSES * 4)       /* 2304 */
#define STAGE_BYTES (SC_BYTES + RK_BYTES)  /* 9216 */

#define NEGF (-1e30f)

__device__ float        g_sum    = 0.0f;
__device__ unsigned int g_cnt    = 0u;
__device__ unsigned int g_ticket = 0u;
__device__ unsigned int g_queue  = 0u;

struct __align__(16) PLShared {
    char stage[STAGES][STAGE_BYTES];
    unsigned long long mbar[STAGES];
    unsigned int races[STAGES];
};

__device__ __forceinline__ uint32_t smem_u32(const void* p) {
    uint32_t a;
    asm("{ .reg .u64 t; cvta.to.shared.u64 t, %1; cvt.u32.u64 %0, t; }"
        : "=r"(a) : "l"(p));
    return a;
}

__device__ __forceinline__ void bulk_g2s(uint32_t dst, const void* src, uint32_t bytes, uint32_t mbar) {
    asm volatile(
        "cp.async.bulk.shared::cluster.global.mbarrier::complete_tx::bytes "
        "[%0], [%1], %2, [%3];"
        :: "r"(dst), "l"(src), "r"(bytes), "r"(mbar) : "memory");
}

__device__ __forceinline__ void mbar_wait(uint32_t mbar, uint32_t parity) {
    asm volatile(
        "{\n\t.reg .pred P;\n"
        "WAIT_%=:\n\t"
        "mbarrier.try_wait.parity.acquire.cta.shared::cta.b64 P, [%0], %1;\n\t"
        "@!P bra WAIT_%=;\n\t}"
        :: "r"(mbar), "r"(parity) : "memory");
}

// lane 0 only: issue TMA for tile `tile` into stage at stageAddr with barrier mbar
__device__ __forceinline__ void issue_tile(uint32_t stageAddr, uint32_t mbar,
                                           const float* scores, const int* ranks,
                                           int tile, int B)
{
    long long start = (long long)tile * TILE;
    int races = min(TILE, B - (int)start);
    uint32_t sc = (uint32_t)races * (HORSES * 3 * 4);
    uint32_t rk = (uint32_t)races * (HORSES * 4);
    asm volatile("mbarrier.arrive.expect_tx.shared.b64 _, [%0], %1;"
                 :: "r"(mbar), "r"(sc + rk) : "memory");
    bulk_g2s(stageAddr,            (const char*)scores + start * (HORSES * 3 * 4), sc, mbar);
    bulk_g2s(stageAddr + SC_BYTES, (const char*)ranks  + start * (HORSES * 4),     rk, mbar);
}

// loss for one race given rank-ordered score values; x* = column 0, y* = column 1
__device__ __forceinline__ float race_loss(int cnt, float x0, float x1, float x2,
                                           float y1, float y2) {
    // p=0: lse{x0,x1,x2} - x0 ; p=1: 0.8*(lse{y1,y2} - y1) ; p=2 term == 0.
    float m   = fmaxf(x0, fmaxf(x1, x2));
    float lse = m + __logf(__expf(x0 - m) + __expf(x1 - m) + __expf(x2 - m));
    float loss = lse - x0;
    if (cnt > 1) {
        float m1 = fmaxf(y1, y2);
        float l1 = m1 + __logf(__expf(y1 - m1) + __expf(y2 - m1));
        loss += 0.8f * (l1 - y1);
    }
    return loss;
}

__global__ void __launch_bounds__(32)
pl_queue(const float* __restrict__ scores,
         const int* __restrict__ ranks,
         float* __restrict__ out,
         int B, int numTiles)
{
    __shared__ PLShared sh;
    const int lane = threadIdx.x;
    const uint32_t stageBase = smem_u32(sh.stage[0]);
    const uint32_t mbarBase  = smem_u32(&sh.mbar[0]);

    if (lane == 0) {
#pragma unroll
        for (int s = 0; s < STAGES; s++) {
            asm volatile("mbarrier.init.shared.b64 [%0], 1;"
                         :: "r"(mbarBase + s * 8) : "memory");
        }
    }
    __syncwarp();

    // ---- prologue: grab and issue up to STAGES tiles ----
    int pending = 0;
#pragma unroll
    for (int s = 0; s < STAGES; s++) {
        int ok = 0;
        if (lane == 0) {
            unsigned t = atomicAdd(&g_queue, 1u);
            if (t < (unsigned)numTiles) {
                ok = 1;
                sh.races[s] = (unsigned)min(TILE, B - (int)t * TILE);
                issue_tile(stageBase + s * STAGE_BYTES, mbarBase + s * 8,
                           scores, ranks, (int)t, B);
            }
        }
        ok = __shfl_sync(0xFFFFFFFFu, ok, 0);
        if (!ok) break;
        pending++;
    }

    float accLoss = 0.0f;
    int   accCnt  = 0;
    int   it = 0;

    while (pending > 0) {
        const int s = it & (STAGES - 1);
        const uint32_t parity = (it >> 2) & 1;
        const uint32_t mbar = mbarBase + s * 8;
        const char* stg = sh.stage[s];

        mbar_wait(mbar, parity);

        const int races = (int)sh.races[s];
        if (lane < races) {
            // ---- pack 18 rank ints (low bytes) into 5 words ----
            const int2* rq = (const int2*)(stg + SC_BYTES + lane * (HORSES * 4));
            int2 q0 = rq[0], q1 = rq[1], q2 = rq[2], q3 = rq[3], q4 = rq[4],
                 q5 = rq[5], q6 = rq[6], q7 = rq[7], q8 = rq[8];

            uint32_t t01 = __byte_perm((uint32_t)q0.x, (uint32_t)q0.y, 0x0040);
            uint32_t t23 = __byte_perm((uint32_t)q1.x, (uint32_t)q1.y, 0x0040);
            uint32_t w0  = __byte_perm(t01, t23, 0x5410);
            uint32_t t45 = __byte_perm((uint32_t)q2.x, (uint32_t)q2.y, 0x0040);
            uint32_t t67 = __byte_perm((uint32_t)q3.x, (uint32_t)q3.y, 0x0040);
            uint32_t w1  = __byte_perm(t45, t67, 0x5410);
            uint32_t t89 = __byte_perm((uint32_t)q4.x, (uint32_t)q4.y, 0x0040);
            uint32_t tab = __byte_perm((uint32_t)q5.x, (uint32_t)q5.y, 0x0040);
            uint32_t w2  = __byte_perm(t89, tab, 0x5410);
            uint32_t tcd = __byte_perm((uint32_t)q6.x, (uint32_t)q6.y, 0x0040);
            uint32_t tef = __byte_perm((uint32_t)q7.x, (uint32_t)q7.y, 0x0040);
            uint32_t w3  = __byte_perm(tcd, tef, 0x5410);
            uint32_t w4  = __byte_perm((uint32_t)q8.x, (uint32_t)q8.y, 0x0040) & 0xFFFFu;

            // ---- horse index of ranks 1,2,3 via per-byte indicators + dp4a ----
            int h1 = 0, h2 = 0, h3 = 0, c1 = 0, c2 = 0, c3 = 0;
#define PL_STEP(W, IDX) do {                                            \
            uint32_t s_ = (W) >> 1;                                     \
            uint32_t b1 = (W) & ~s_ & 0x01010101u;                      \
            uint32_t b2 = ~(W) & s_ & 0x01010101u;                      \
            uint32_t b3 = (W) & s_ & 0x01010101u;                       \
            h1 = __dp4a((int)b1, (int)(IDX), h1); c1 = __dp4a((int)b1, 0x01010101, c1); \
            h2 = __dp4a((int)b2, (int)(IDX), h2); c2 = __dp4a((int)b2, 0x01010101, c2); \
            h3 = __dp4a((int)b3, (int)(IDX), h3); c3 = __dp4a((int)b3, 0x01010101, c3); \
        } while (0)
            PL_STEP(w0, 0x03020100);
            PL_STEP(w1, 0x07060504);
            PL_STEP(w2, 0x0B0A0908);
            PL_STEP(w3, 0x0F0E0D0C);
            PL_STEP(w4, 0x13121110);
#undef PL_STEP

            bool p1 = (c1 > 0), p2 = (c2 > 0), p3 = (c3 > 0);
            int cnt = (int)p1 + (int)p2 + (int)p3;
            int e23 = p2 ? h2 : h3;
            int hs0 = p1 ? h1 : e23;
            int hs1 = p1 ? e23 : h3;
            int hs2 = h3;

            const float* sb = (const float*)stg + lane * (HORSES * 3);
            float x0  = sb[hs0 * 3];
            float x1v = sb[hs1 * 3];
            float y1v = sb[hs1 * 3 + 1];
            float x2v = sb[hs2 * 3];
            float y2v = sb[hs2 * 3 + 1];

            float x1 = (cnt > 1) ? x1v : NEGF;
            float x2 = (cnt > 2) ? x2v : NEGF;
            float y1 = (cnt > 1) ? y1v : 0.0f;
            float y2 = (cnt > 2) ? y2v : NEGF;

            if (cnt > 0) {
                accCnt++;
                accLoss += race_loss(cnt, x0, x1, x2, y1, y2);
            }
        }

        __syncwarp();   // whole warp done reading stage s
        pending--;

        // ---- refill stage s with next tile from the queue ----
        int ok = 0;
        if (lane == 0) {
            unsigned t = atomicAdd(&g_queue, 1u);
            if (t < (unsigned)numTiles) {
                ok = 1;
                sh.races[s] = (unsigned)min(TILE, B - (int)t * TILE);
                issue_tile(stageBase + s * STAGE_BYTES, mbar, scores, ranks, (int)t, B);
            }
        }
        ok = __shfl_sync(0xFFFFFFFFu, ok, 0);
        if (ok) pending++;
        it++;
    }

    // ---- warp reduction + finalize ----
    float v = accLoss;
    int   c = accCnt;
#pragma unroll
    for (int o = 16; o; o >>= 1) {
        v += __shfl_xor_sync(0xFFFFFFFFu, v, o);
        c += __shfl_xor_sync(0xFFFFFFFFu, c, o);
    }
    if (lane == 0) {
        atomicAdd(&g_sum, v);
        atomicAdd(&g_cnt, (unsigned int)c);
        __threadfence();
        unsigned t = atomicAdd(&g_ticket, 1u);
        if (t == gridDim.x - 1) {
            // last CTA: read + reset ALL globals (state identical for next replay)
            float sum  = atomicExch(&g_sum, 0.0f);
            unsigned n = atomicExch(&g_cnt, 0u);
            atomicExch(&g_queue, 0u);
            atomicExch(&g_ticket, 0u);
            out[0] = sum / fmaxf((float)n, 1.0f);
        }
    }
}

extern "C" void kernel_launch(void* const* d_in, const int* in_sizes, int n_in,
                              void* d_out, int out_size)
{
    const float* scores = (const float*)d_in[0];
    const int*   ranks  = (const int*)d_in[1];

    int B = in_sizes[1] / HORSES;
    int numTiles = (B + TILE - 1) / TILE;

    int grid = CTAS_PER_SM * NUM_SMS;
    if (grid > numTiles) grid = numTiles;
    if (grid < 1) grid = 1;

    pl_queue<<<grid, 32>>>(scores, ranks, (float*)d_out, B, numTiles);
}